// round 2
// baseline (speedup 1.0000x reference)
#include <cuda_runtime.h>
#include <cuda_bf16.h>

// Problem shape
#define BATCH 1024
#define HEADS 16
#define SEQ   8
#define DKDIM 32
#define NHEAD (BATCH * HEADS)            // 16384 heads
#define HEAD_ELEMS (SEQ * DKDIM)         // 256 floats per head tensor
#define CTX_ELEMS  (NHEAD * HEAD_ELEMS)  // 4194304
#define W_ELEMS    (NHEAD * SEQ * SEQ)   // 1048576

#define WARPS_PER_BLOCK 8
#define THREADS (WARPS_PER_BLOCK * 32)

__device__ __forceinline__ float warp8_max(float v) {
    // reduce over 8-lane aligned groups
    v = fmaxf(v, __shfl_xor_sync(0xFFFFFFFFu, v, 1));
    v = fmaxf(v, __shfl_xor_sync(0xFFFFFFFFu, v, 2));
    v = fmaxf(v, __shfl_xor_sync(0xFFFFFFFFu, v, 4));
    return v;
}
__device__ __forceinline__ float warp8_sum(float v) {
    v += __shfl_xor_sync(0xFFFFFFFFu, v, 1);
    v += __shfl_xor_sync(0xFFFFFFFFu, v, 2);
    v += __shfl_xor_sync(0xFFFFFFFFu, v, 4);
    return v;
}

__global__ __launch_bounds__(THREADS)
void sdpa_kernel(const float* __restrict__ Qg,
                 const float* __restrict__ Kg,
                 const float* __restrict__ Vg,
                 const int* __restrict__ Mg,   // bool mask materialized as int32
                 const float* __restrict__ Hg,
                 float* __restrict__ ctx_out,
                 float* __restrict__ w_out)
{
    // pad 33 -> score-loop reads of sK[k][d] hit distinct banks per k
    __shared__ float sQ[WARPS_PER_BLOCK][SEQ][33];
    __shared__ float sK[WARPS_PER_BLOCK][SEQ][33];
    __shared__ float sV[WARPS_PER_BLOCK][SEQ][33];
    __shared__ float sW[WARPS_PER_BLOCK][SEQ][9];   // pad 9 -> conflict-free q reads

    const int w    = threadIdx.x >> 5;
    const int lane = threadIdx.x & 31;
    const int hid  = blockIdx.x * WARPS_PER_BLOCK + w;
    if (hid >= NHEAD) return;

    const float INV_SQRT_DK = 0.17677669529663687f;  // 1/sqrt(32)

    // ---- stage Q,K,V (256 floats each) into shared, float4-coalesced ----
    const float4* Q4 = (const float4*)(Qg + (size_t)hid * HEAD_ELEMS);
    const float4* K4 = (const float4*)(Kg + (size_t)hid * HEAD_ELEMS);
    const float4* V4 = (const float4*)(Vg + (size_t)hid * HEAD_ELEMS);

    #pragma unroll
    for (int t = lane; t < 64; t += 32) {      // 64 float4 per tensor
        const int row = t >> 3;                // t*4/32
        const int col = (t & 7) << 2;
        float4 q = Q4[t];
        float4 k = K4[t];
        float4 v = V4[t];
        sQ[w][row][col+0]=q.x; sQ[w][row][col+1]=q.y; sQ[w][row][col+2]=q.z; sQ[w][row][col+3]=q.w;
        sK[w][row][col+0]=k.x; sK[w][row][col+1]=k.y; sK[w][row][col+2]=k.z; sK[w][row][col+3]=k.w;
        sV[w][row][col+0]=v.x; sV[w][row][col+1]=v.y; sV[w][row][col+2]=v.z; sV[w][row][col+3]=v.w;
    }
    __syncwarp();

    // ---- scores: 64 (q,k) pairs, 2 per lane ----
    const int p0 = lane;        // q0 = p0>>3 in 0..3
    const int p1 = lane + 32;   // q1 = p1>>3 in 4..7
    const int q0 = p0 >> 3, k0 = p0 & 7;
    const int q1 = p1 >> 3, k1 = p1 & 7;

    // issue mask loads early (independent of the dot products)
    const int* m = Mg + (size_t)hid * 64;
    const int m0 = m[p0];
    const int m1 = m[p1];

    float s0 = 0.f, s1 = 0.f;
    #pragma unroll
    for (int d = 0; d < DKDIM; d++) {
        s0 += sQ[w][q0][d] * sK[w][k0][d];
        s1 += sQ[w][q1][d] * sK[w][k1][d];
    }

    // mask: where(mask, -1e9, score*scale)
    s0 = m0 ? -1e9f : s0 * INV_SQRT_DK;
    s1 = m1 ? -1e9f : s1 * INV_SQRT_DK;

    // ---- softmax over k (8 consecutive lanes == one q row) ----
    float mx0 = warp8_max(s0);
    float mx1 = warp8_max(s1);
    float e0 = __expf(s0 - mx0);
    float e1 = __expf(s1 - mx1);
    float den0 = warp8_sum(e0);
    float den1 = warp8_sum(e1);
    float w0 = e0 / den0;
    float w1 = e1 / den1;

    // weights output (coalesced: lane -> +p0, +p1)
    float* wo = w_out + (size_t)hid * 64;
    wo[p0] = w0;
    wo[p1] = w1;

    sW[w][q0][k0] = w0;
    sW[w][q1][k1] = w1;
    __syncwarp();

    // ---- context: lane -> (q = lane>>2, d chunk = (lane&3)*8) ----
    const int cq = lane >> 2;
    const int cd = (lane & 3) << 3;

    float acc[8];
    #pragma unroll
    for (int j = 0; j < 8; j++) acc[j] = 0.f;

    #pragma unroll
    for (int k = 0; k < SEQ; k++) {
        const float wk = sW[w][cq][k];
        #pragma unroll
        for (int j = 0; j < 8; j++)
            acc[j] += wk * sV[w][k][cd + j];
    }

    // post-scale by hyper, float4 stores (each lane owns 8 contiguous floats)
    const size_t obase = (size_t)hid * HEAD_ELEMS + cq * DKDIM + cd;
    const float4* h4 = (const float4*)(Hg + obase);
    float4 ha = h4[0], hb = h4[1];
    float4 oa, ob;
    oa.x = acc[0]*ha.x; oa.y = acc[1]*ha.y; oa.z = acc[2]*ha.z; oa.w = acc[3]*ha.w;
    ob.x = acc[4]*hb.x; ob.y = acc[5]*hb.y; ob.z = acc[6]*hb.z; ob.w = acc[7]*hb.w;
    float4* o4 = (float4*)(ctx_out + obase);
    o4[0] = oa;
    o4[1] = ob;
}

extern "C" void kernel_launch(void* const* d_in, const int* in_sizes, int n_in,
                              void* d_out, int out_size) {
    const float* Q  = (const float*)d_in[0];
    const float* K  = (const float*)d_in[1];
    const float* V  = (const float*)d_in[2];
    const int*   M  = (const int*)d_in[3];
    const float* Hy = (const float*)d_in[4];

    float* ctx = (float*)d_out;                 // [B,H,S,DK] flattened, first
    float* wts = ctx + CTX_ELEMS;               // [B,H,S,S] flattened, second

    const int blocks = NHEAD / WARPS_PER_BLOCK; // 2048
    sdpa_kernel<<<blocks, THREADS>>>(Q, K, V, M, Hy, ctx, wts);
}

// round 4
// speedup vs baseline: 1.1204x; 1.1204x over previous
#include <cuda_runtime.h>
#include <cuda_bf16.h>

// Problem shape
#define BATCH 1024
#define HEADS 16
#define SEQ   8
#define DKDIM 32
#define NHEAD (BATCH * HEADS)            // 16384 heads
#define HEAD_ELEMS (SEQ * DKDIM)         // 256 floats per head tensor
#define CTX_ELEMS  (NHEAD * HEAD_ELEMS)  // 4194304
#define W_ELEMS    (NHEAD * SEQ * SEQ)   // 1048576

#define WARPS_PER_BLOCK 8
#define THREADS (WARPS_PER_BLOCK * 32)
#define ROWPAD 36   // floats per row: 144B, 16B-aligned, +4 banks/row

__device__ __forceinline__ float warp8_max(float v) {
    v = fmaxf(v, __shfl_xor_sync(0xFFFFFFFFu, v, 1));
    v = fmaxf(v, __shfl_xor_sync(0xFFFFFFFFu, v, 2));
    v = fmaxf(v, __shfl_xor_sync(0xFFFFFFFFu, v, 4));
    return v;
}
__device__ __forceinline__ float warp8_sum(float v) {
    v += __shfl_xor_sync(0xFFFFFFFFu, v, 1);
    v += __shfl_xor_sync(0xFFFFFFFFu, v, 2);
    v += __shfl_xor_sync(0xFFFFFFFFu, v, 4);
    return v;
}

__global__ __launch_bounds__(THREADS)
void sdpa_kernel(const float* __restrict__ Qg,
                 const float* __restrict__ Kg,
                 const float* __restrict__ Vg,
                 const int* __restrict__ Mg,   // bool mask materialized as int32
                 const float* __restrict__ Hg,
                 float* __restrict__ ctx_out,
                 float* __restrict__ w_out)
{
    __shared__ float sQ[WARPS_PER_BLOCK][SEQ][ROWPAD];
    __shared__ float sK[WARPS_PER_BLOCK][SEQ][ROWPAD];
    __shared__ float sV[WARPS_PER_BLOCK][SEQ][ROWPAD];
    __shared__ float sW[WARPS_PER_BLOCK][SEQ][8];   // 32B rows, 16B-aligned

    const int w    = threadIdx.x >> 5;
    const int lane = threadIdx.x & 31;
    const int hid  = blockIdx.x * WARPS_PER_BLOCK + w;

    const float INV_SQRT_DK = 0.17677669529663687f;  // 1/sqrt(32)

    // ---- early independent global loads (MLP) ----
    const int p0 = lane;        // (q0,k0)
    const int p1 = lane + 32;   // (q1,k1); note k1 == k0
    const int q0 = p0 >> 3, k0 = p0 & 7;
    const int q1 = p1 >> 3;

    const int* m = Mg + (size_t)hid * 64;
    const int m0 = m[p0];
    const int m1 = m[p1];

    // hyper for this lane's context chunk: q = lane>>2, d in [ (lane&3)*8, +8 )
    const int cq  = lane >> 2;
    const int cd4 = (lane & 3) << 1;                 // float4 slot (2 per lane)
    const size_t obase = (size_t)hid * HEAD_ELEMS + cq * DKDIM + (cd4 << 2);
    const float4* h4 = (const float4*)(Hg + obase);
    const float4 ha = h4[0], hb = h4[1];

    // ---- stage Q,K,V into shared with STS.128 ----
    const float4* Q4 = (const float4*)(Qg + (size_t)hid * HEAD_ELEMS);
    const float4* K4 = (const float4*)(Kg + (size_t)hid * HEAD_ELEMS);
    const float4* V4 = (const float4*)(Vg + (size_t)hid * HEAD_ELEMS);

    #pragma unroll
    for (int t = lane; t < 64; t += 32) {      // 64 float4 per tensor
        const int row = t >> 3;
        const int c4  = t & 7;                 // float4 slot within row
        ((float4*)&sQ[w][row][0])[c4] = Q4[t];
        ((float4*)&sK[w][row][0])[c4] = K4[t];
        ((float4*)&sV[w][row][0])[c4] = V4[t];
    }
    __syncwarp();

    // ---- scores: vectorized dot products (one K row feeds both scores) ----
    const float4* qa = (const float4*)&sQ[w][q0][0];
    const float4* qb = (const float4*)&sQ[w][q1][0];
    const float4* kr = (const float4*)&sK[w][k0][0];

    float4 a0 = make_float4(0.f,0.f,0.f,0.f);
    float4 a1 = make_float4(0.f,0.f,0.f,0.f);
    #pragma unroll
    for (int j = 0; j < 8; j++) {
        const float4 kv = kr[j];
        const float4 qv0 = qa[j];
        const float4 qv1 = qb[j];
        a0.x += qv0.x*kv.x; a0.y += qv0.y*kv.y; a0.z += qv0.z*kv.z; a0.w += qv0.w*kv.w;
        a1.x += qv1.x*kv.x; a1.y += qv1.y*kv.y; a1.z += qv1.z*kv.z; a1.w += qv1.w*kv.w;
    }
    float s0 = (a0.x + a0.y) + (a0.z + a0.w);
    float s1 = (a1.x + a1.y) + (a1.z + a1.w);

    s0 = m0 ? -1e9f : s0 * INV_SQRT_DK;
    s1 = m1 ? -1e9f : s1 * INV_SQRT_DK;

    // ---- softmax over k (8 consecutive lanes == one q row) ----
    const float mx0 = warp8_max(s0);
    const float mx1 = warp8_max(s1);
    const float e0 = __expf(s0 - mx0);
    const float e1 = __expf(s1 - mx1);
    const float w0 = e0 / warp8_sum(e0);
    const float w1 = e1 / warp8_sum(e1);

    // weights output (coalesced)
    float* wo = w_out + (size_t)hid * 64;
    wo[p0] = w0;
    wo[p1] = w1;

    // sW[q][k]: p0 -> flat index lane, p1 -> lane+32: both conflict-free
    sW[w][q0][k0] = w0;
    sW[w][q1][k0] = w1;
    __syncwarp();

    // ---- context: lane owns (q=cq, 8 floats at d=cd4*4) ----
    const float4* wrow = (const float4*)&sW[w][cq][0];
    const float4 wv0 = wrow[0], wv1 = wrow[1];
    const float wreg[8] = { wv0.x, wv0.y, wv0.z, wv0.w, wv1.x, wv1.y, wv1.z, wv1.w };

    float4 acc0 = make_float4(0.f,0.f,0.f,0.f);
    float4 acc1 = make_float4(0.f,0.f,0.f,0.f);
    #pragma unroll
    for (int k = 0; k < SEQ; k++) {
        const float4* vr = (const float4*)&sV[w][k][0] + cd4;
        const float4 va = vr[0];
        const float4 vb = vr[1];
        const float wk = wreg[k];
        acc0.x += wk*va.x; acc0.y += wk*va.y; acc0.z += wk*va.z; acc0.w += wk*va.w;
        acc1.x += wk*vb.x; acc1.y += wk*vb.y; acc1.z += wk*vb.z; acc1.w += wk*vb.w;
    }

    float4 oa, ob;
    oa.x = acc0.x*ha.x; oa.y = acc0.y*ha.y; oa.z = acc0.z*ha.z; oa.w = acc0.w*ha.w;
    ob.x = acc1.x*hb.x; ob.y = acc1.y*hb.y; ob.z = acc1.z*hb.z; ob.w = acc1.w*hb.w;
    float4* o4 = (float4*)(ctx_out + obase);
    o4[0] = oa;
    o4[1] = ob;
}

extern "C" void kernel_launch(void* const* d_in, const int* in_sizes, int n_in,
                              void* d_out, int out_size) {
    const float* Q  = (const float*)d_in[0];
    const float* K  = (const float*)d_in[1];
    const float* V  = (const float*)d_in[2];
    const int*   M  = (const int*)d_in[3];
    const float* Hy = (const float*)d_in[4];

    float* ctx = (float*)d_out;                 // [B,H,S,DK] flattened, first
    float* wts = ctx + CTX_ELEMS;               // [B,H,S,S] flattened, second

    const int blocks = NHEAD / WARPS_PER_BLOCK; // 2048
    sdpa_kernel<<<blocks, THREADS>>>(Q, K, V, M, Hy, ctx, wts);
}